// round 13
// baseline (speedup 1.0000x reference)
#include <cuda_runtime.h>
#include <cuda_fp16.h>
#include <cuda_bf16.h>

// Problem constants (B=1)
#define L_   1024
#define H_   2048
#define DI_  4096
#define NS_  16
#define R_   128
#define NCAT 160   // R_ + NS_ + NS_

// ---------------- scratch (no allocations allowed) ----------------
__device__ __align__(256) float g_hs_raw[DI_ * L_];
__device__ __align__(256) float g_gate  [DI_ * L_];
__device__ __align__(256) float g_hs    [DI_ * L_];
__device__ __align__(256) float g_dt    [DI_ * L_];
__device__ __align__(256) float g_wcat  [NCAT * DI_];
__device__ __align__(256) float g_pcat  [8 * L_ * NCAT];
__device__ __align__(256) float g_cat   [L_ * NCAT];
__device__ __align__(256) float g_ygT   [L_ * DI_];   // [L, DI]

__device__ __forceinline__ float softplusf(float x) {
    return x > 15.f ? x : log1pf(__expf(x));
}
__device__ __forceinline__ float siluf(float v) {
    return v * (1.f / (1.f + __expf(-v)));
}

// ---------------- split-fp16 tensor-core TN GEMM, double-buffered smem ----------------
// C[m,n] = sum_k A[m*lda+k] * B[n*ldb+k].
// x = hi + lo (fp16 each, residual 2^-22); product = hi*hi (fp32 acc)
//   + (hi*lo + lo*hi) accumulated in fp16 (fast path), flushed per 16-k chunk.
// BM=BN=128, BK=16 (8 f16x2 words), 256 threads = 8 warps (4m x 2n),
// warp tile 32m x 64n, mma.m16n8k16. One __syncthreads per k-tile.
// epi=1: softplus(acc + bias[m]).
#define TBM 128
#define TBN 128
#define TBK 16
#define AST 12   // 8 data words + 4 pad: (g*12+t) mod 32 all-distinct over a warp

// pack two floats -> f16x2 word, even element in low half
__device__ __forceinline__ unsigned packh(float e, float o) {
    unsigned w;
    asm("cvt.rn.f16x2.f32 %0, %1, %2;" : "=r"(w) : "f"(o), "f"(e));
    return w;
}
// fp16 hi/lo split of an (even,odd) float pair
__device__ __forceinline__ void split2(float e, float o, unsigned& hi, unsigned& lo) {
    hi = packh(e, o);
    __half2 h = *reinterpret_cast<__half2*>(&hi);
    float2 f = __half22float2(h);          // f.x = even(hi), f.y = odd(hi)
    lo = packh(e - f.x, o - f.y);
}

// main term: fp16 inputs, fp32 accumulate
__device__ __forceinline__ void mma_main(float* c, const unsigned* a, const unsigned* b) {
    asm volatile(
        "mma.sync.aligned.m16n8k16.row.col.f32.f16.f16.f32 "
        "{%0,%1,%2,%3}, {%4,%5,%6,%7}, {%8,%9}, {%0,%1,%2,%3};"
        : "+f"(c[0]), "+f"(c[1]), "+f"(c[2]), "+f"(c[3])
        : "r"(a[0]), "r"(a[1]), "r"(a[2]), "r"(a[3]),
          "r"(b[0]), "r"(b[1]));
}
// cross terms: fp16 inputs, fp16 accumulate (possible 2x-rate path)
__device__ __forceinline__ void mma_cross(unsigned& c0, unsigned& c1,
                                          const unsigned* a, const unsigned* b) {
    asm volatile(
        "mma.sync.aligned.m16n8k16.row.col.f16.f16.f16.f16 "
        "{%0,%1}, {%2,%3,%4,%5}, {%6,%7}, {%0,%1};"
        : "+r"(c0), "+r"(c1)
        : "r"(a[0]), "r"(a[1]), "r"(a[2]), "r"(a[3]),
          "r"(b[0]), "r"(b[1]));
}

__global__ __launch_bounds__(256) void gemm_f16_tn(
    const float* __restrict__ A, const float* __restrict__ B,
    float* __restrict__ C, const float* __restrict__ bias,
    int K, int lda, int ldb, int ldc, int epi)
{
    __shared__ unsigned As_hi[2][TBM * AST];
    __shared__ unsigned As_lo[2][TBM * AST];
    __shared__ unsigned Bs_hi[2][TBN * AST];
    __shared__ unsigned Bs_lo[2][TBN * AST];

    const int tid  = threadIdx.x;
    const int lane = tid & 31;
    const int w    = tid >> 5;
    const int wm   = w >> 1;         // 0..3
    const int wn   = w & 1;          // 0..1
    const int g    = lane >> 2;      // 0..7
    const int t    = lane & 3;       // 0..3
    const int m0   = blockIdx.y * TBM;
    const int n0   = blockIdx.x * TBN;

    // staging: thread handles row r, k-range [half*8, half*8+8)
    const int r    = tid >> 1;       // 0..127
    const int half = tid & 1;        // 0 or 1
    const float* Ap = A + (m0 + r) * lda + half * 8;
    const float* Bp = B + (n0 + r) * ldb + half * 8;
    const int soff  = r * AST + half * 4;

    float c[2][8][4];
#pragma unroll
    for (int mi = 0; mi < 2; mi++)
#pragma unroll
        for (int ni = 0; ni < 8; ni++)
#pragma unroll
            for (int j = 0; j < 4; j++) c[mi][ni][j] = 0.f;

    float4 va0 = *(const float4*)(Ap);
    float4 va1 = *(const float4*)(Ap + 4);
    float4 vb0 = *(const float4*)(Bp);
    float4 vb1 = *(const float4*)(Bp + 4);

    // stage tile0 -> buf0
    {
        unsigned h0, l0, h1, l1;
        split2(va0.x, va0.y, h0, l0); split2(va0.z, va0.w, h1, l1);
        *(uint2*)&As_hi[0][soff] = make_uint2(h0, h1);
        *(uint2*)&As_lo[0][soff] = make_uint2(l0, l1);
        split2(va1.x, va1.y, h0, l0); split2(va1.z, va1.w, h1, l1);
        *(uint2*)&As_hi[0][soff + 2] = make_uint2(h0, h1);
        *(uint2*)&As_lo[0][soff + 2] = make_uint2(l0, l1);
        split2(vb0.x, vb0.y, h0, l0); split2(vb0.z, vb0.w, h1, l1);
        *(uint2*)&Bs_hi[0][soff] = make_uint2(h0, h1);
        *(uint2*)&Bs_lo[0][soff] = make_uint2(l0, l1);
        split2(vb1.x, vb1.y, h0, l0); split2(vb1.z, vb1.w, h1, l1);
        *(uint2*)&Bs_hi[0][soff + 2] = make_uint2(h0, h1);
        *(uint2*)&Bs_lo[0][soff + 2] = make_uint2(l0, l1);
    }
    if (TBK < K) {
        va0 = *(const float4*)(Ap + TBK);
        va1 = *(const float4*)(Ap + TBK + 4);
        vb0 = *(const float4*)(Bp + TBK);
        vb1 = *(const float4*)(Bp + TBK + 4);
    }
    __syncthreads();

    int p = 0;
    for (int k0 = 0; k0 < K; k0 += TBK) {
        // stage next tile into other buffer; prefetch the one after
        if (k0 + TBK < K) {
            unsigned h0, l0, h1, l1;
            split2(va0.x, va0.y, h0, l0); split2(va0.z, va0.w, h1, l1);
            *(uint2*)&As_hi[p ^ 1][soff] = make_uint2(h0, h1);
            *(uint2*)&As_lo[p ^ 1][soff] = make_uint2(l0, l1);
            split2(va1.x, va1.y, h0, l0); split2(va1.z, va1.w, h1, l1);
            *(uint2*)&As_hi[p ^ 1][soff + 2] = make_uint2(h0, h1);
            *(uint2*)&As_lo[p ^ 1][soff + 2] = make_uint2(l0, l1);
            split2(vb0.x, vb0.y, h0, l0); split2(vb0.z, vb0.w, h1, l1);
            *(uint2*)&Bs_hi[p ^ 1][soff] = make_uint2(h0, h1);
            *(uint2*)&Bs_lo[p ^ 1][soff] = make_uint2(l0, l1);
            split2(vb1.x, vb1.y, h0, l0); split2(vb1.z, vb1.w, h1, l1);
            *(uint2*)&Bs_hi[p ^ 1][soff + 2] = make_uint2(h0, h1);
            *(uint2*)&Bs_lo[p ^ 1][soff + 2] = make_uint2(l0, l1);
            if (k0 + 2 * TBK < K) {
                va0 = *(const float4*)(Ap + k0 + 2 * TBK);
                va1 = *(const float4*)(Ap + k0 + 2 * TBK + 4);
                vb0 = *(const float4*)(Bp + k0 + 2 * TBK);
                vb1 = *(const float4*)(Bp + k0 + 2 * TBK + 4);
            }
        }

        // compute from buf[p]
        unsigned ahi[2][4], alo[2][4];
#pragma unroll
        for (int mi = 0; mi < 2; mi++) {
            int ra = (wm * 32 + mi * 16 + g) * AST + t;
            int rb = ra + 8 * AST;
            ahi[mi][0] = As_hi[p][ra];     ahi[mi][1] = As_hi[p][rb];
            ahi[mi][2] = As_hi[p][ra + 4]; ahi[mi][3] = As_hi[p][rb + 4];
            alo[mi][0] = As_lo[p][ra];     alo[mi][1] = As_lo[p][rb];
            alo[mi][2] = As_lo[p][ra + 4]; alo[mi][3] = As_lo[p][rb + 4];
        }
#pragma unroll
        for (int ni = 0; ni < 8; ni++) {
            int rbb = (wn * 64 + ni * 8 + g) * AST + t;
            unsigned bhi[2], blo[2];
            bhi[0] = Bs_hi[p][rbb]; bhi[1] = Bs_hi[p][rbb + 4];
            blo[0] = Bs_lo[p][rbb]; blo[1] = Bs_lo[p][rbb + 4];
#pragma unroll
            for (int mi = 0; mi < 2; mi++) {
                mma_main(c[mi][ni], ahi[mi], bhi);
                unsigned cr0 = 0u, cr1 = 0u;
                mma_cross(cr0, cr1, ahi[mi], blo);
                mma_cross(cr0, cr1, alo[mi], bhi);
                float2 f0 = __half22float2(*reinterpret_cast<__half2*>(&cr0));
                float2 f1 = __half22float2(*reinterpret_cast<__half2*>(&cr1));
                c[mi][ni][0] += f0.x; c[mi][ni][1] += f0.y;
                c[mi][ni][2] += f1.x; c[mi][ni][3] += f1.y;
            }
        }
        __syncthreads();
        p ^= 1;
    }

    // epilogue
#pragma unroll
    for (int mi = 0; mi < 2; mi++) {
        int row0 = m0 + wm * 32 + mi * 16 + g;
        int row1 = row0 + 8;
        float b0v = epi ? bias[row0] : 0.f;
        float b1v = epi ? bias[row1] : 0.f;
#pragma unroll
        for (int ni = 0; ni < 8; ni++) {
            int col = n0 + wn * 64 + ni * 8 + t * 2;
            float v0 = c[mi][ni][0], v1 = c[mi][ni][1];
            float v2 = c[mi][ni][2], v3 = c[mi][ni][3];
            if (epi) {
                v0 = softplusf(v0 + b0v); v1 = softplusf(v1 + b0v);
                v2 = softplusf(v2 + b1v); v3 = softplusf(v3 + b1v);
            }
            *(float2*)&C[row0 * ldc + col] = make_float2(v0, v1);
            *(float2*)&C[row1 * ldc + col] = make_float2(v2, v3);
        }
    }
}

// ---------------- causal depthwise conv (K=4) + bias + SiLU, float4 over l ----------------
__global__ void conv_silu_kernel(const float* __restrict__ hs_raw,
                                 const float* __restrict__ w,
                                 const float* __restrict__ b,
                                 float* __restrict__ hs)
{
    int i = blockIdx.x * blockDim.x + threadIdx.x;
    int d = i >> 8;
    int l0 = (i & 255) * 4;
    const float* row = hs_raw + d * L_;
    float w0 = w[d * 4 + 0], w1 = w[d * 4 + 1], w2 = w[d * 4 + 2], w3 = w[d * 4 + 3];
    float bb = b[d];
    float4 xc = *(const float4*)(row + l0);
    float xm1, xm2, xm3;
    if (l0 >= 4) {
        float4 xp = *(const float4*)(row + l0 - 4);
        xm1 = xp.w; xm2 = xp.z; xm3 = xp.y;
    } else {
        xm1 = xm2 = xm3 = 0.f;
    }
    float4 o;
    o.x = siluf(fmaf(w3, xc.x, fmaf(w2, xm1, fmaf(w1, xm2, fmaf(w0, xm3, bb)))));
    o.y = siluf(fmaf(w3, xc.y, fmaf(w2, xc.x, fmaf(w1, xm1, fmaf(w0, xm2, bb)))));
    o.z = siluf(fmaf(w3, xc.z, fmaf(w2, xc.y, fmaf(w1, xc.x, fmaf(w0, xm1, bb)))));
    o.w = siluf(fmaf(w3, xc.w, fmaf(w2, xc.z, fmaf(w1, xc.y, fmaf(w0, xc.x, bb)))));
    *(float4*)(hs + d * L_ + l0) = o;
}

// ---------------- concat [W_dt; W_b; W_c] -> Wcat [160, DI] ----------------
__global__ void concat_w_kernel(const float* __restrict__ Wdt,
                                const float* __restrict__ Wb,
                                const float* __restrict__ Wc,
                                float* __restrict__ Wcat)
{
    int i = blockIdx.x * blockDim.x + threadIdx.x;
    int n = i / DI_;
    int k = i - n * DI_;
    float v;
    if (n < R_)            v = Wdt[i];
    else if (n < R_ + NS_) v = Wb[(n - R_) * DI_ + k];
    else                   v = Wc[(n - R_ - NS_) * DI_ + k];
    Wcat[i] = v;
}

// ---------------- skinny split-K GEMM: cat[l,n] = sum_d hs[d,l]*Wcat[n,d] ----
#define SK_BM 128
#define SK_BN 32
#define SK_BK 32
#define SK_KCHUNK 512
__global__ __launch_bounds__(256) void gemm_skinny(
    const float* __restrict__ A, const float* __restrict__ Bw,
    float* __restrict__ P, int M, int lda, int ldb)
{
    __shared__ __align__(16) float As[SK_BK][SK_BM];
    __shared__ float Bs[SK_BK][SK_BN + 1];
    int tid = threadIdx.x;
    int m0 = blockIdx.x * SK_BM;
    int n0 = blockIdx.y * SK_BN;
    int kbase = blockIdx.z * SK_KCHUNK;
    int tn = tid & 15;
    int tm = tid >> 4;
    float acc[8][2];
#pragma unroll
    for (int i = 0; i < 8; i++) { acc[i][0] = 0.f; acc[i][1] = 0.f; }

    for (int k0 = kbase; k0 < kbase + SK_KCHUNK; k0 += SK_BK) {
        __syncthreads();
        {
            int mq = (tid & 31) * 4;
            int krb = tid >> 5;
#pragma unroll
            for (int s = 0; s < 4; s++) {
                int kr = krb + s * 8;
                float4 v = *(const float4*)(A + (k0 + kr) * lda + m0 + mq);
                *(float4*)&As[kr][mq] = v;
            }
        }
        {
            int nr = tid >> 3;
            int kq = (tid & 7) * 4;
            float4 v = *(const float4*)(Bw + (n0 + nr) * ldb + k0 + kq);
            Bs[kq + 0][nr] = v.x; Bs[kq + 1][nr] = v.y;
            Bs[kq + 2][nr] = v.z; Bs[kq + 3][nr] = v.w;
        }
        __syncthreads();
#pragma unroll
        for (int kk = 0; kk < SK_BK; kk++) {
            float4 a0 = *(const float4*)&As[kk][tm * 8];
            float4 a1 = *(const float4*)&As[kk][tm * 8 + 4];
            float b0 = Bs[kk][tn * 2];
            float b1 = Bs[kk][tn * 2 + 1];
            float ar[8] = {a0.x, a0.y, a0.z, a0.w, a1.x, a1.y, a1.z, a1.w};
#pragma unroll
            for (int i = 0; i < 8; i++) {
                acc[i][0] = fmaf(ar[i], b0, acc[i][0]);
                acc[i][1] = fmaf(ar[i], b1, acc[i][1]);
            }
        }
    }
    float* Pp = P + blockIdx.z * (M * NCAT);
#pragma unroll
    for (int i = 0; i < 8; i++) {
        int m = m0 + tm * 8 + i;
        float2 v = make_float2(acc[i][0], acc[i][1]);
        *(float2*)&Pp[m * NCAT + n0 + tn * 2] = v;
    }
}

__global__ void reduce_cat_kernel(const float* __restrict__ P, float* __restrict__ cat)
{
    int i = blockIdx.x * blockDim.x + threadIdx.x;
    float s = 0.f;
#pragma unroll
    for (int sp = 0; sp < 8; sp++) s += P[sp * (L_ * NCAT) + i];
    cat[i] = s;
}

// ---------------- selective scan: warp handles 2 channels, 16 lanes = 16 states ----
__global__ __launch_bounds__(256) void scan_kernel(
    const float* __restrict__ dt, const float* __restrict__ hs,
    const float* __restrict__ gate, const float* __restrict__ cat,
    const float* __restrict__ A_log, const float* __restrict__ Dvec,
    float* __restrict__ ygT)
{
    int warp = threadIdx.x >> 5;
    int lane = threadIdx.x & 31;
    int half = lane >> 4;
    int ln = lane & 15;
    int d = blockIdx.x * 16 + warp * 2 + half;

    float a = -__expf(A_log[d * NS_ + ln]);
    float Dd = Dvec[d];
    float s = 0.f;
    const float* dtp = dt + d * L_;
    const float* hsp = hs + d * L_;
    const float* gp  = gate + d * L_;
    const float* bp  = cat + R_ + ln;
    const float* cp  = cat + R_ + NS_ + ln;
    float* yp = ygT + d;

    for (int l = 0; l < L_; l++) {
        float dtv = dtp[l];
        float hsv = hsp[l];
        float bn = bp[l * NCAT];
        float cn = cp[l * NCAT];
        float dA = __expf(a * dtv);
        s = fmaf(dA, s, dtv * bn * hsv);
        float p = s * cn;
        p += __shfl_xor_sync(0xffffffffu, p, 8);
        p += __shfl_xor_sync(0xffffffffu, p, 4);
        p += __shfl_xor_sync(0xffffffffu, p, 2);
        p += __shfl_xor_sync(0xffffffffu, p, 1);
        if (ln == 0) {
            float gv = gp[l];
            float y = fmaf(hsv, Dd, p);
            y *= siluf(gv);
            yp[l * DI_] = y;
        }
    }
}

// ---------------- host launcher ----------------
extern "C" void kernel_launch(void* const* d_in, const int* in_sizes, int n_in,
                              void* d_out, int out_size)
{
    const float* x     = (const float*)d_in[0];   // [1, L, H]
    const float* Wis   = (const float*)d_in[1];   // [DI, H]
    const float* Wig   = (const float*)d_in[2];   // [DI, H]
    const float* convw = (const float*)d_in[3];   // [DI, 4]
    const float* convb = (const float*)d_in[4];   // [DI]
    const float* Wdt   = (const float*)d_in[5];   // [R, DI]
    const float* Wb    = (const float*)d_in[6];   // [N, DI]
    const float* Wc    = (const float*)d_in[7];   // [N, DI]
    const float* Wdtp  = (const float*)d_in[8];   // [DI, R]
    const float* bdtp  = (const float*)d_in[9];   // [DI]
    const float* Alog  = (const float*)d_in[10];  // [DI, N]
    const float* Dv    = (const float*)d_in[11];  // [DI]
    const float* Wout  = (const float*)d_in[12];  // [H, DI]
    float* out = (float*)d_out;                   // [1, L, H]

    float *hs_raw, *gate, *hs, *dtb, *wcat, *pcat, *cat, *ygT;
    cudaGetSymbolAddress((void**)&hs_raw, g_hs_raw);
    cudaGetSymbolAddress((void**)&gate,   g_gate);
    cudaGetSymbolAddress((void**)&hs,     g_hs);
    cudaGetSymbolAddress((void**)&dtb,    g_dt);
    cudaGetSymbolAddress((void**)&wcat,   g_wcat);
    cudaGetSymbolAddress((void**)&pcat,   g_pcat);
    cudaGetSymbolAddress((void**)&cat,    g_cat);
    cudaGetSymbolAddress((void**)&ygT,    g_ygT);

    dim3 blk(256);

    // 1-2. input projections: hs_raw/gate [DI, L] = W @ x^T  (split-fp16 MMA)
    gemm_f16_tn<<<dim3(L_ / TBN, DI_ / TBM), blk>>>(Wis, x, hs_raw, nullptr,
                                                    H_, H_, H_, L_, 0);
    gemm_f16_tn<<<dim3(L_ / TBN, DI_ / TBM), blk>>>(Wig, x, gate, nullptr,
                                                    H_, H_, H_, L_, 0);
    // 3. causal depthwise conv + SiLU (float4 over l)
    conv_silu_kernel<<<(DI_ * L_ / 4) / 256, 256>>>(hs_raw, convw, convb, hs);
    // 4. concat W_dt/W_b/W_c
    concat_w_kernel<<<(NCAT * DI_) / 256, 256>>>(Wdt, Wb, Wc, wcat);
    // 5. ts/B/C fused skinny GEMM (split-K, deterministic reduce)
    gemm_skinny<<<dim3(L_ / SK_BM, NCAT / SK_BN, 8), blk>>>(hs, wcat, pcat, L_, L_, DI_);
    reduce_cat_kernel<<<(L_ * NCAT) / 256, 256>>>(pcat, cat);
    // 6. dt [DI, L] = softplus(W_dtproj @ ts^T + b)  (split-fp16, K=128)
    gemm_f16_tn<<<dim3(L_ / TBN, DI_ / TBM), blk>>>(Wdtp, cat, dtb, bdtp,
                                                    R_, R_, NCAT, L_, 1);
    // 7. selective scan (+D skip, +silu(gate) multiply) -> ygT [L, DI]
    scan_kernel<<<DI_ / 16, 256>>>(dtb, hs, gate, cat, Alog, Dv, ygT);
    // 8. out [L, H] = ygT @ W_out^T  (split-fp16)
    gemm_f16_tn<<<dim3(H_ / TBN, L_ / TBM), blk>>>(ygT, Wout, out, nullptr,
                                                   DI_, DI_, DI_, H_, 0);
}

// round 14
// speedup vs baseline: 1.1269x; 1.1269x over previous
#include <cuda_runtime.h>
#include <cuda_bf16.h>
#include <cstdint>

// Problem constants (B=1)
#define L_   1024
#define H_   2048
#define DI_  4096
#define NS_  16
#define R_   128
#define NCAT 160   // R_ + NS_ + NS_

// ---------------- scratch (no allocations allowed) ----------------
__device__ __align__(256) float g_hs_raw[DI_ * L_];
__device__ __align__(256) float g_gate  [DI_ * L_];
__device__ __align__(256) float g_hs    [DI_ * L_];
__device__ __align__(256) float g_dt    [DI_ * L_];
__device__ __align__(256) float g_wcat  [NCAT * DI_];
__device__ __align__(256) float g_pcat  [8 * L_ * NCAT];
__device__ __align__(256) float g_cat   [L_ * NCAT];
__device__ __align__(256) float g_ygT   [L_ * DI_];   // [L, DI]

__device__ __forceinline__ float softplusf(float x) {
    return x > 15.f ? x : log1pf(__expf(x));
}
__device__ __forceinline__ float siluf(float v) {
    return v * (1.f / (1.f + __expf(-v)));
}

// ---------------- split-bf16 tensor-core TN GEMM, ldmatrix fragments ----------------
// C[m,n] = sum_k A[m*lda+k] * B[n*ldb+k].
// x = hi + lo (bf16 each); product = hi*hi + hi*lo + lo*hi (error ~2^-18).
// BM=BN=128, BK=16, 256 threads = 8 warps (4m x 2n), warp tile 32m x 64n,
// mma.m16n8k16, double-buffered smem, one __syncthreads per k-tile.
// Fragment loads via ldmatrix.m8n8.x4 (12 LDSM/warp-chunk instead of 48 LDS).
// epi=1: softplus(acc + bias[m]).
#define TBM 128
#define TBN 128
#define TBK 16
#define AST 12   // 8 data words + 4 pad: rows 48B apart, conflict-free phases
#define BUFB (TBM * AST * 4)   // bytes per buffer plane

// pack two floats -> bf16x2 word, even k in low half
__device__ __forceinline__ unsigned packbf(float e, float o) {
    unsigned w;
    asm("cvt.rn.bf16x2.f32 %0, %1, %2;" : "=r"(w) : "f"(o), "f"(e));
    return w;
}
__device__ __forceinline__ void split2(float e, float o, unsigned& hi, unsigned& lo) {
    hi = packbf(e, o);
    float he = __uint_as_float(hi << 16);
    float ho = __uint_as_float(hi & 0xffff0000u);
    lo = packbf(e - he, o - ho);
}

__device__ __forceinline__ void mma_bf16(float* c, const unsigned* a, const unsigned* b) {
    asm volatile(
        "mma.sync.aligned.m16n8k16.row.col.f32.bf16.bf16.f32 "
        "{%0,%1,%2,%3}, {%4,%5,%6,%7}, {%8,%9}, {%0,%1,%2,%3};"
        : "+f"(c[0]), "+f"(c[1]), "+f"(c[2]), "+f"(c[3])
        : "r"(a[0]), "r"(a[1]), "r"(a[2]), "r"(a[3]),
          "r"(b[0]), "r"(b[1]));
}

#define LDSM4(r0, r1, r2, r3, addr) \
    asm volatile("ldmatrix.sync.aligned.m8n8.x4.shared.b16 {%0,%1,%2,%3}, [%4];" \
                 : "=r"(r0), "=r"(r1), "=r"(r2), "=r"(r3) : "r"(addr))

__global__ __launch_bounds__(256) void gemm_bf16_tn(
    const float* __restrict__ A, const float* __restrict__ B,
    float* __restrict__ C, const float* __restrict__ bias,
    int K, int lda, int ldb, int ldc, int epi, int yoff)
{
    __shared__ unsigned As_hi[2][TBM * AST];
    __shared__ unsigned As_lo[2][TBM * AST];
    __shared__ unsigned Bs_hi[2][TBN * AST];
    __shared__ unsigned Bs_lo[2][TBN * AST];

    const int tid  = threadIdx.x;
    const int lane = tid & 31;
    const int w    = tid >> 5;
    const int wm   = w >> 1;         // 0..3
    const int wn   = w & 1;          // 0..1
    const int g    = lane >> 2;      // 0..7
    const int t    = lane & 3;       // 0..3
    const int m0   = (blockIdx.y + yoff) * TBM;
    const int n0   = blockIdx.x * TBN;

    // staging: thread handles row r, k-range [half*8, half*8+8)
    const int r    = tid >> 1;       // 0..127
    const int half = tid & 1;        // 0 or 1
    const float* Ap = A + (m0 + r) * lda + half * 8;
    const float* Bp = B + (n0 + r) * ldb + half * 8;
    const int soff  = r * AST + half * 4;

    // ldmatrix per-lane byte offsets (within one buffer plane)
    // A (.x4 per mi): lanes 0-15 rows m0-15 (kw 0); 16-31 same rows (kw 4)
    const uint32_t offA = ((uint32_t)((wm * 32 + (lane & 15)) * AST
                          + ((lane >> 4) & 1) * 4)) * 4u;
    // B (.x4 per ni-pair): lanes 0-7 rows n0-7 kw0; 8-15 n0-7 kw4;
    //                      16-23 n8-15 kw0; 24-31 n8-15 kw4
    const uint32_t offB = ((uint32_t)((wn * 64 + ((lane >> 4) & 1) * 8 + (lane & 7)) * AST
                          + ((lane >> 3) & 1) * 4)) * 4u;
    const uint32_t bAhi = (uint32_t)__cvta_generic_to_shared(&As_hi[0][0]) + offA;
    const uint32_t bAlo = (uint32_t)__cvta_generic_to_shared(&As_lo[0][0]) + offA;
    const uint32_t bBhi = (uint32_t)__cvta_generic_to_shared(&Bs_hi[0][0]) + offB;
    const uint32_t bBlo = (uint32_t)__cvta_generic_to_shared(&Bs_lo[0][0]) + offB;

    float c[2][8][4];
#pragma unroll
    for (int mi = 0; mi < 2; mi++)
#pragma unroll
        for (int ni = 0; ni < 8; ni++)
#pragma unroll
            for (int j = 0; j < 4; j++) c[mi][ni][j] = 0.f;

    float4 va0 = *(const float4*)(Ap);
    float4 va1 = *(const float4*)(Ap + 4);
    float4 vb0 = *(const float4*)(Bp);
    float4 vb1 = *(const float4*)(Bp + 4);

    // stage tile0 -> buf0
    {
        unsigned h0, l0, h1, l1;
        split2(va0.x, va0.y, h0, l0); split2(va0.z, va0.w, h1, l1);
        *(uint2*)&As_hi[0][soff] = make_uint2(h0, h1);
        *(uint2*)&As_lo[0][soff] = make_uint2(l0, l1);
        split2(va1.x, va1.y, h0, l0); split2(va1.z, va1.w, h1, l1);
        *(uint2*)&As_hi[0][soff + 2] = make_uint2(h0, h1);
        *(uint2*)&As_lo[0][soff + 2] = make_uint2(l0, l1);
        split2(vb0.x, vb0.y, h0, l0); split2(vb0.z, vb0.w, h1, l1);
        *(uint2*)&Bs_hi[0][soff] = make_uint2(h0, h1);
        *(uint2*)&Bs_lo[0][soff] = make_uint2(l0, l1);
        split2(vb1.x, vb1.y, h0, l0); split2(vb1.z, vb1.w, h1, l1);
        *(uint2*)&Bs_hi[0][soff + 2] = make_uint2(h0, h1);
        *(uint2*)&Bs_lo[0][soff + 2] = make_uint2(l0, l1);
    }
    if (TBK < K) {
        va0 = *(const float4*)(Ap + TBK);
        va1 = *(const float4*)(Ap + TBK + 4);
        vb0 = *(const float4*)(Bp + TBK);
        vb1 = *(const float4*)(Bp + TBK + 4);
    }
    __syncthreads();

    int p = 0;
    for (int k0 = 0; k0 < K; k0 += TBK) {
        // stage next tile into other buffer; prefetch the one after
        if (k0 + TBK < K) {
            unsigned h0, l0, h1, l1;
            split2(va0.x, va0.y, h0, l0); split2(va0.z, va0.w, h1, l1);
            *(uint2*)&As_hi[p ^ 1][soff] = make_uint2(h0, h1);
            *(uint2*)&As_lo[p ^ 1][soff] = make_uint2(l0, l1);
            split2(va1.x, va1.y, h0, l0); split2(va1.z, va1.w, h1, l1);
            *(uint2*)&As_hi[p ^ 1][soff + 2] = make_uint2(h0, h1);
            *(uint2*)&As_lo[p ^ 1][soff + 2] = make_uint2(l0, l1);
            split2(vb0.x, vb0.y, h0, l0); split2(vb0.z, vb0.w, h1, l1);
            *(uint2*)&Bs_hi[p ^ 1][soff] = make_uint2(h0, h1);
            *(uint2*)&Bs_lo[p ^ 1][soff] = make_uint2(l0, l1);
            split2(vb1.x, vb1.y, h0, l0); split2(vb1.z, vb1.w, h1, l1);
            *(uint2*)&Bs_hi[p ^ 1][soff + 2] = make_uint2(h0, h1);
            *(uint2*)&Bs_lo[p ^ 1][soff + 2] = make_uint2(l0, l1);
            if (k0 + 2 * TBK < K) {
                va0 = *(const float4*)(Ap + k0 + 2 * TBK);
                va1 = *(const float4*)(Ap + k0 + 2 * TBK + 4);
                vb0 = *(const float4*)(Bp + k0 + 2 * TBK);
                vb1 = *(const float4*)(Bp + k0 + 2 * TBK + 4);
            }
        }

        // compute from buf[p] via ldmatrix
        const uint32_t pb = (uint32_t)(p * BUFB);
        unsigned ahi[2][4], alo[2][4];
#pragma unroll
        for (int mi = 0; mi < 2; mi++) {
            LDSM4(ahi[mi][0], ahi[mi][1], ahi[mi][2], ahi[mi][3],
                  bAhi + pb + mi * (16 * AST * 4));
            LDSM4(alo[mi][0], alo[mi][1], alo[mi][2], alo[mi][3],
                  bAlo + pb + mi * (16 * AST * 4));
        }
#pragma unroll
        for (int n2 = 0; n2 < 4; n2++) {
            unsigned bh[4], bl[4];
            LDSM4(bh[0], bh[1], bh[2], bh[3], bBhi + pb + n2 * (16 * AST * 4));
            LDSM4(bl[0], bl[1], bl[2], bl[3], bBlo + pb + n2 * (16 * AST * 4));
#pragma unroll
            for (int mi = 0; mi < 2; mi++) {
                mma_bf16(c[mi][n2 * 2],     ahi[mi], bh);
                mma_bf16(c[mi][n2 * 2],     ahi[mi], bl);
                mma_bf16(c[mi][n2 * 2],     alo[mi], bh);
                mma_bf16(c[mi][n2 * 2 + 1], ahi[mi], bh + 2);
                mma_bf16(c[mi][n2 * 2 + 1], ahi[mi], bl + 2);
                mma_bf16(c[mi][n2 * 2 + 1], alo[mi], bh + 2);
            }
        }
        __syncthreads();
        p ^= 1;
    }

    // epilogue
#pragma unroll
    for (int mi = 0; mi < 2; mi++) {
        int row0 = m0 + wm * 32 + mi * 16 + g;
        int row1 = row0 + 8;
        float b0v = epi ? bias[row0] : 0.f;
        float b1v = epi ? bias[row1] : 0.f;
#pragma unroll
        for (int ni = 0; ni < 8; ni++) {
            int col = n0 + wn * 64 + ni * 8 + t * 2;
            float v0 = c[mi][ni][0], v1 = c[mi][ni][1];
            float v2 = c[mi][ni][2], v3 = c[mi][ni][3];
            if (epi) {
                v0 = softplusf(v0 + b0v); v1 = softplusf(v1 + b0v);
                v2 = softplusf(v2 + b1v); v3 = softplusf(v3 + b1v);
            }
            *(float2*)&C[row0 * ldc + col] = make_float2(v0, v1);
            *(float2*)&C[row1 * ldc + col] = make_float2(v2, v3);
        }
    }
}

// ---------------- causal depthwise conv (K=4) + bias + SiLU, float4 over l ----------------
__global__ void conv_silu_kernel(const float* __restrict__ hs_raw,
                                 const float* __restrict__ w,
                                 const float* __restrict__ b,
                                 float* __restrict__ hs)
{
    int i = blockIdx.x * blockDim.x + threadIdx.x;
    int d = i >> 8;
    int l0 = (i & 255) * 4;
    const float* row = hs_raw + d * L_;
    float w0 = w[d * 4 + 0], w1 = w[d * 4 + 1], w2 = w[d * 4 + 2], w3 = w[d * 4 + 3];
    float bb = b[d];
    float4 xc = *(const float4*)(row + l0);
    float xm1, xm2, xm3;
    if (l0 >= 4) {
        float4 xp = *(const float4*)(row + l0 - 4);
        xm1 = xp.w; xm2 = xp.z; xm3 = xp.y;
    } else {
        xm1 = xm2 = xm3 = 0.f;
    }
    float4 o;
    o.x = siluf(fmaf(w3, xc.x, fmaf(w2, xm1, fmaf(w1, xm2, fmaf(w0, xm3, bb)))));
    o.y = siluf(fmaf(w3, xc.y, fmaf(w2, xc.x, fmaf(w1, xm1, fmaf(w0, xm2, bb)))));
    o.z = siluf(fmaf(w3, xc.z, fmaf(w2, xc.y, fmaf(w1, xc.x, fmaf(w0, xm1, bb)))));
    o.w = siluf(fmaf(w3, xc.w, fmaf(w2, xc.z, fmaf(w1, xc.y, fmaf(w0, xc.x, bb)))));
    *(float4*)(hs + d * L_ + l0) = o;
}

// ---------------- concat [W_dt; W_b; W_c] -> Wcat [160, DI] ----------------
__global__ void concat_w_kernel(const float* __restrict__ Wdt,
                                const float* __restrict__ Wb,
                                const float* __restrict__ Wc,
                                float* __restrict__ Wcat)
{
    int i = blockIdx.x * blockDim.x + threadIdx.x;
    int n = i / DI_;
    int k = i - n * DI_;
    float v;
    if (n < R_)            v = Wdt[i];
    else if (n < R_ + NS_) v = Wb[(n - R_) * DI_ + k];
    else                   v = Wc[(n - R_ - NS_) * DI_ + k];
    Wcat[i] = v;
}

// ---------------- skinny split-K GEMM: cat[l,n] = sum_d hs[d,l]*Wcat[n,d] ----
#define SK_BM 128
#define SK_BN 32
#define SK_BK 32
#define SK_KCHUNK 512
__global__ __launch_bounds__(256) void gemm_skinny(
    const float* __restrict__ A, const float* __restrict__ Bw,
    float* __restrict__ P, int M, int lda, int ldb)
{
    __shared__ __align__(16) float As[SK_BK][SK_BM];
    __shared__ float Bs[SK_BK][SK_BN + 1];
    int tid = threadIdx.x;
    int m0 = blockIdx.x * SK_BM;
    int n0 = blockIdx.y * SK_BN;
    int kbase = blockIdx.z * SK_KCHUNK;
    int tn = tid & 15;
    int tm = tid >> 4;
    float acc[8][2];
#pragma unroll
    for (int i = 0; i < 8; i++) { acc[i][0] = 0.f; acc[i][1] = 0.f; }

    for (int k0 = kbase; k0 < kbase + SK_KCHUNK; k0 += SK_BK) {
        __syncthreads();
        {
            int mq = (tid & 31) * 4;
            int krb = tid >> 5;
#pragma unroll
            for (int s = 0; s < 4; s++) {
                int kr = krb + s * 8;
                float4 v = *(const float4*)(A + (k0 + kr) * lda + m0 + mq);
                *(float4*)&As[kr][mq] = v;
            }
        }
        {
            int nr = tid >> 3;
            int kq = (tid & 7) * 4;
            float4 v = *(const float4*)(Bw + (n0 + nr) * ldb + k0 + kq);
            Bs[kq + 0][nr] = v.x; Bs[kq + 1][nr] = v.y;
            Bs[kq + 2][nr] = v.z; Bs[kq + 3][nr] = v.w;
        }
        __syncthreads();
#pragma unroll
        for (int kk = 0; kk < SK_BK; kk++) {
            float4 a0 = *(const float4*)&As[kk][tm * 8];
            float4 a1 = *(const float4*)&As[kk][tm * 8 + 4];
            float b0 = Bs[kk][tn * 2];
            float b1 = Bs[kk][tn * 2 + 1];
            float ar[8] = {a0.x, a0.y, a0.z, a0.w, a1.x, a1.y, a1.z, a1.w};
#pragma unroll
            for (int i = 0; i < 8; i++) {
                acc[i][0] = fmaf(ar[i], b0, acc[i][0]);
                acc[i][1] = fmaf(ar[i], b1, acc[i][1]);
            }
        }
    }
    float* Pp = P + blockIdx.z * (M * NCAT);
#pragma unroll
    for (int i = 0; i < 8; i++) {
        int m = m0 + tm * 8 + i;
        float2 v = make_float2(acc[i][0], acc[i][1]);
        *(float2*)&Pp[m * NCAT + n0 + tn * 2] = v;
    }
}

__global__ void reduce_cat_kernel(const float* __restrict__ P, float* __restrict__ cat)
{
    int i = blockIdx.x * blockDim.x + threadIdx.x;
    float s = 0.f;
#pragma unroll
    for (int sp = 0; sp < 8; sp++) s += P[sp * (L_ * NCAT) + i];
    cat[i] = s;
}

// ---------------- selective scan: warp handles 2 channels, 16 lanes = 16 states ----
__global__ __launch_bounds__(256) void scan_kernel(
    const float* __restrict__ dt, const float* __restrict__ hs,
    const float* __restrict__ gate, const float* __restrict__ cat,
    const float* __restrict__ A_log, const float* __restrict__ Dvec,
    float* __restrict__ ygT)
{
    int warp = threadIdx.x >> 5;
    int lane = threadIdx.x & 31;
    int half = lane >> 4;
    int ln = lane & 15;
    int d = blockIdx.x * 16 + warp * 2 + half;

    float a = -__expf(A_log[d * NS_ + ln]);
    float Dd = Dvec[d];
    float s = 0.f;
    const float* dtp = dt + d * L_;
    const float* hsp = hs + d * L_;
    const float* gp  = gate + d * L_;
    const float* bp  = cat + R_ + ln;
    const float* cp  = cat + R_ + NS_ + ln;
    float* yp = ygT + d;

    for (int l = 0; l < L_; l++) {
        float dtv = dtp[l];
        float hsv = hsp[l];
        float bn = bp[l * NCAT];
        float cn = cp[l * NCAT];
        float dA = __expf(a * dtv);
        s = fmaf(dA, s, dtv * bn * hsv);
        float p = s * cn;
        p += __shfl_xor_sync(0xffffffffu, p, 8);
        p += __shfl_xor_sync(0xffffffffu, p, 4);
        p += __shfl_xor_sync(0xffffffffu, p, 2);
        p += __shfl_xor_sync(0xffffffffu, p, 1);
        if (ln == 0) {
            float gv = gp[l];
            float y = fmaf(hsv, Dd, p);
            y *= siluf(gv);
            yp[l * DI_] = y;
        }
    }
}

// ---------------- host launcher ----------------
extern "C" void kernel_launch(void* const* d_in, const int* in_sizes, int n_in,
                              void* d_out, int out_size)
{
    const float* x     = (const float*)d_in[0];   // [1, L, H]
    const float* Wis   = (const float*)d_in[1];   // [DI, H]
    const float* Wig   = (const float*)d_in[2];   // [DI, H]
    const float* convw = (const float*)d_in[3];   // [DI, 4]
    const float* convb = (const float*)d_in[4];   // [DI]
    const float* Wdt   = (const float*)d_in[5];   // [R, DI]
    const float* Wb    = (const float*)d_in[6];   // [N, DI]
    const float* Wc    = (const float*)d_in[7];   // [N, DI]
    const float* Wdtp  = (const float*)d_in[8];   // [DI, R]
    const float* bdtp  = (const float*)d_in[9];   // [DI]
    const float* Alog  = (const float*)d_in[10];  // [DI, N]
    const float* Dv    = (const float*)d_in[11];  // [DI]
    const float* Wout  = (const float*)d_in[12];  // [H, DI]
    float* out = (float*)d_out;                   // [1, L, H]

    float *hs_raw, *gate, *hs, *dtb, *wcat, *pcat, *cat, *ygT;
    cudaGetSymbolAddress((void**)&hs_raw, g_hs_raw);
    cudaGetSymbolAddress((void**)&gate,   g_gate);
    cudaGetSymbolAddress((void**)&hs,     g_hs);
    cudaGetSymbolAddress((void**)&dtb,    g_dt);
    cudaGetSymbolAddress((void**)&wcat,   g_wcat);
    cudaGetSymbolAddress((void**)&pcat,   g_pcat);
    cudaGetSymbolAddress((void**)&cat,    g_cat);
    cudaGetSymbolAddress((void**)&ygT,    g_ygT);

    dim3 blk(256);

    // Launch order chosen so the 4th launch (the one ncu captures) is a full
    // input-projection GEMM.
    // 1. concat W_dt/W_b/W_c (independent of everything else)
    concat_w_kernel<<<(NCAT * DI_) / 256, 256>>>(Wdt, Wb, Wc, wcat);
    // 2-3. hs_raw in-projection, split into two half-grids
    gemm_bf16_tn<<<dim3(L_ / TBN, DI_ / TBM / 2), blk>>>(Wis, x, hs_raw, nullptr,
                                                         H_, H_, H_, L_, 0, 0);
    gemm_bf16_tn<<<dim3(L_ / TBN, DI_ / TBM / 2), blk>>>(Wis, x, hs_raw, nullptr,
                                                         H_, H_, H_, L_, 0, DI_ / TBM / 2);
    // 4. gate in-projection  <-- profiled launch
    gemm_bf16_tn<<<dim3(L_ / TBN, DI_ / TBM), blk>>>(Wig, x, gate, nullptr,
                                                     H_, H_, H_, L_, 0, 0);
    // 5. causal depthwise conv + SiLU
    conv_silu_kernel<<<(DI_ * L_ / 4) / 256, 256>>>(hs_raw, convw, convb, hs);
    // 6-7. ts/B/C fused skinny GEMM (split-K, deterministic reduce)
    gemm_skinny<<<dim3(L_ / SK_BM, NCAT / SK_BN, 8), blk>>>(hs, wcat, pcat, L_, L_, DI_);
    reduce_cat_kernel<<<(L_ * NCAT) / 256, 256>>>(pcat, cat);
    // 8. dt [DI, L] = softplus(W_dtproj @ ts^T + b)
    gemm_bf16_tn<<<dim3(L_ / TBN, DI_ / TBM), blk>>>(Wdtp, cat, dtb, bdtp,
                                                     R_, R_, NCAT, L_, 1, 0);
    // 9. selective scan -> ygT [L, DI]
    scan_kernel<<<DI_ / 16, 256>>>(dtb, hs, gate, cat, Alog, Dv, ygT);
    // 10. out [L, H] = ygT @ W_out^T
    gemm_bf16_tn<<<dim3(H_ / TBN, L_ / TBM), blk>>>(ygT, Wout, out, nullptr,
                                                    DI_, DI_, DI_, H_, 0, 0);
}